// round 16
// baseline (speedup 1.0000x reference)
#include <cuda_runtime.h>
#include <cuda_fp16.h>
#include <cstdint>

#define HIDDEN   128
#define OUT      256
#define NRAD     6
#define TM       64                 // rows per CTA tile (2 CTAs/SM)
#define KCH      64                 // K elements per chunk
#define KPC      (KCH/2)            // 32 k-pairs per chunk
#define ASTRIDE2 132   // u32 stride, mod 32 = 4 -> a-frag banks 4g+q distinct
#define BSTRIDE2 264   // u32 stride (>=256 cols), mod 32 = 8 -> b-frag banks 8q+g distinct
#define CHUNK_U32 (KPC * OUT)       // 8192 u32 = 32KB per chunk image
#define NCHUNKS  14                 // 2 (layer0 K=128) + 3*4 (K=256)
#define NODES_MAX 50176
#define E_MAX    1048576

__device__ float    g_hbuf[(size_t)NODES_MAX * HIDDEN];   // node accumulator (gather output)
__device__ uint32_t g_wt[(size_t)NCHUNKS * CHUNK_U32];    // fp16x2 weights [chunk][kpair][n]
__device__ int      g_is64;
__device__ int      g_cnt[NODES_MAX];   // per-node degree
__device__ int      g_off[NODES_MAX];   // exclusive offsets
__device__ int      g_cur[NODES_MAX];   // running cursor for permute
__device__ int      g_bsum[256];        // per-scan-block sums
__device__ int      g_perm[E_MAX];      // node-sorted edge ids

__device__ __forceinline__ void cp_async16(uint32_t dst_smem, const void* src) {
    asm volatile("cp.async.cg.shared.global [%0], [%1], 16;" :: "r"(dst_smem), "l"(src) : "memory");
}
__device__ __forceinline__ void cp_commit() {
    asm volatile("cp.async.commit_group;" ::: "memory");
}
template <int N>
__device__ __forceinline__ void cp_wait() {
    asm volatile("cp.async.wait_group %0;" :: "n"(N) : "memory");
}
__device__ __forceinline__ uint32_t smem_u32(const void* p) {
    uint32_t a;
    asm("{ .reg .u64 t; cvta.to.shared.u64 t, %1; cvt.u32.u64 %0, t; }" : "=r"(a) : "l"(p));
    return a;
}
__device__ __forceinline__ void mma16(float* c, const uint32_t* a, const uint32_t* b) {
    asm volatile("mma.sync.aligned.m16n8k16.row.col.f32.f16.f16.f32 "
                 "{%0,%1,%2,%3}, {%4,%5,%6,%7}, {%8,%9}, {%0,%1,%2,%3};"
                 : "+f"(c[0]), "+f"(c[1]), "+f"(c[2]), "+f"(c[3])
                 : "r"(a[0]), "r"(a[1]), "r"(a[2]), "r"(a[3]),
                   "r"(b[0]), "r"(b[1]));
}
__device__ __forceinline__ uint32_t pack_h2(float lo, float hi) {
    __half2 h = __floats2half2_rn(lo, hi);
    return *(uint32_t*)&h;
}
__device__ __forceinline__ long long load_node(const void* idxp, int e) {
    return (g_is64 != 0) ? __ldg(((const long long*)idxp) + e)
                         : (long long)__ldg(((const int*)idxp) + e);
}

// ---------------------------------------------------------------------------
// prep: (a) index dtype detection; (b) weights -> fp16x2 k-pair-packed chunks
// ---------------------------------------------------------------------------
__global__ void prep_kernel(const float* __restrict__ Wd, const float* __restrict__ Ws,
                            const long long* __restrict__ idx, int n_nodes) {
    if (blockIdx.x == 0 && threadIdx.x < 32) {
        long long v = idx[threadIdx.x];
        unsigned ok = __ballot_sync(0xFFFFFFFFu, v >= 0 && v < (long long)n_nodes);
        if (threadIdx.x == 0) g_is64 = (ok == 0xFFFFFFFFu) ? 1 : 0;
    }
    int u = blockIdx.x * blockDim.x + threadIdx.x;
    if (u >= NCHUNKS * CHUNK_U32) return;
    int gch = u / CHUNK_U32;
    int rem = u % CHUNK_U32;
    int kp  = rem >> 8;
    int n   = rem & 255;
    int layer, c;
    if (gch < 2) { layer = 0; c = gch; } else { layer = 1 + (gch - 2) / 4; c = (gch - 2) % 4; }
    int k0 = c * KCH + 2 * kp;
    const float* W = (layer == 0) ? Wd : (Ws + (size_t)(layer - 1) * OUT * OUT);
    g_wt[u] = pack_h2(W[(size_t)k0 * OUT + n], W[(size_t)(k0 + 1) * OUT + n]);
}

// ---------------------------------------------------------------------------
// CSR build: count -> scan (3 tiny kernels) -> permute
// ---------------------------------------------------------------------------
__global__ void count_kernel(const void* __restrict__ idxp, int E) {
    int e = blockIdx.x * blockDim.x + threadIdx.x;
    if (e < E) atomicAdd(&g_cnt[(int)load_node(idxp, e)], 1);
}

__global__ void scanA_kernel(int nb) {   // per-block sums of g_cnt
    __shared__ int s[256];
    int i = blockIdx.x * 256 + threadIdx.x;
    s[threadIdx.x] = g_cnt[i];
    __syncthreads();
    for (int d = 128; d > 0; d >>= 1) {
        if (threadIdx.x < d) s[threadIdx.x] += s[threadIdx.x + d];
        __syncthreads();
    }
    if (threadIdx.x == 0) g_bsum[blockIdx.x] = s[0];
}

__global__ void scanB_kernel(int nb) {   // exclusive scan of block sums (nb <= 256)
    __shared__ int s[256];
    int v = (threadIdx.x < nb) ? g_bsum[threadIdx.x] : 0;
    s[threadIdx.x] = v;
    __syncthreads();
    for (int d = 1; d < 256; d <<= 1) {
        int t = (threadIdx.x >= d) ? s[threadIdx.x - d] : 0;
        __syncthreads();
        s[threadIdx.x] += t;
        __syncthreads();
    }
    if (threadIdx.x < nb) g_bsum[threadIdx.x] = s[threadIdx.x] - v;  // exclusive
}

__global__ void scanC_kernel(int nb) {   // per-element exclusive offsets
    __shared__ int s[256];
    int i = blockIdx.x * 256 + threadIdx.x;
    int v = g_cnt[i];
    s[threadIdx.x] = v;
    __syncthreads();
    for (int d = 1; d < 256; d <<= 1) {
        int t = (threadIdx.x >= d) ? s[threadIdx.x - d] : 0;
        __syncthreads();
        s[threadIdx.x] += t;
        __syncthreads();
    }
    int excl = s[threadIdx.x] - v + g_bsum[blockIdx.x];
    g_off[i] = excl;
    g_cur[i] = excl;
}

__global__ void permute_kernel(const void* __restrict__ idxp, int E) {
    int e = blockIdx.x * blockDim.x + threadIdx.x;
    if (e >= E) return;
    int node = (int)load_node(idxp, e);
    int slot = atomicAdd(&g_cur[node], 1);
    g_perm[slot] = e;
}

// ---------------------------------------------------------------------------
// gather: one warp per node, register accumulation, single store. No atomics.
// ---------------------------------------------------------------------------
__global__ void gather_kernel(const float* __restrict__ x,
                              const float* __restrict__ rbf,
                              const float* __restrict__ W_rbf,
                              int n_nodes) {
    const int lane = threadIdx.x & 31;
    const int node = (blockIdx.x * blockDim.x + threadIdx.x) >> 5;
    if (node >= n_nodes) return;
    const int c0 = lane * 4;

    float w[NRAD][4];
#pragma unroll
    for (int r = 0; r < NRAD; r++)
#pragma unroll
        for (int j = 0; j < 4; j++) w[r][j] = __ldg(&W_rbf[r * HIDDEN + c0 + j]);

    const int off = g_off[node];
    const int deg = g_cnt[node];
    float acc[4] = {0.f, 0.f, 0.f, 0.f};

    auto edge = [&](int eid) {
        const float2* rp = (const float2*)(rbf + (size_t)eid * NRAD);
        float2 ra = __ldg(rp), rb = __ldg(rp + 1), rc = __ldg(rp + 2);
        float4 xv = __ldcs((const float4*)(x + (size_t)eid * HIDDEN + c0));
        float xc[4] = {xv.x, xv.y, xv.z, xv.w};
#pragma unroll
        for (int j = 0; j < 4; j++) {
            float s = ra.x * w[0][j];
            s = fmaf(ra.y, w[1][j], s); s = fmaf(rb.x, w[2][j], s);
            s = fmaf(rb.y, w[3][j], s); s = fmaf(rc.x, w[4][j], s);
            s = fmaf(rc.y, w[5][j], s);
            acc[j] = fmaf(s, xc[j], acc[j]);
        }
    };

    int t = 0;
    for (; t + 2 <= deg; t += 2) {        // 2-edge ILP: both eids in flight
        int e0 = __ldg(&g_perm[off + t]);
        int e1 = __ldg(&g_perm[off + t + 1]);
        edge(e0);
        edge(e1);
    }
    if (t < deg) edge(__ldg(&g_perm[off + t]));

    *(float4*)(g_hbuf + (size_t)node * HIDDEN + c0) =
        make_float4(acc[0], acc[1], acc[2], acc[3]);
}

// ---------------------------------------------------------------------------
// fused 4-layer MLP (unchanged from the 245.8us kernel)
// ---------------------------------------------------------------------------
__global__ __launch_bounds__(256, 2)
void mlp_kernel(const float* __restrict__ bs, float* __restrict__ out, int n_nodes) {
    extern __shared__ uint32_t smem[];
    uint32_t* As = smem;                           // [64][ASTRIDE2] half2
    uint32_t* Bs = smem + TM * ASTRIDE2;           // [2][KPC][BSTRIDE2] half2
    const uint32_t bs_smem = smem_u32(Bs);

    const int tid  = threadIdx.x;
    const int row0 = blockIdx.x * TM;

    auto stage = [&](int gchunk) {
        const int buf = gchunk & 1;
        const char* src = (const char*)(g_wt + (size_t)gchunk * CHUNK_U32);
#pragma unroll
        for (int j = 0; j < 8; j++) {
            int idx  = tid + j * 256;
            int row  = idx >> 6;
            int c16  = idx & 63;
            uint32_t dst = bs_smem
                         + (uint32_t)(buf * KPC * BSTRIDE2 + row * BSTRIDE2) * 4 + c16 * 16;
            cp_async16(dst, src + row * 1024 + c16 * 16);
        }
        cp_commit();
    };

    stage(0);

    for (int t = tid; t < TM * (HIDDEN / 4); t += 256) {
        int r  = t >> 5;
        int c4 = (t & 31) << 2;
        float4 v = make_float4(0.f, 0.f, 0.f, 0.f);
        if (row0 + r < n_nodes)
            v = *(const float4*)(g_hbuf + (size_t)(row0 + r) * HIDDEN + c4);
        uint32_t* d = As + r * ASTRIDE2 + (c4 >> 1);
        d[0] = pack_h2(v.x, v.y);
        d[1] = pack_h2(v.z, v.w);
    }
    __syncthreads();

    const int lane = tid & 31;
    const int w    = tid >> 5;
    const int wm   = (w & 1) << 5;
    const int wn   = (w >> 1) << 6;
    const int g    = lane >> 2;
    const int q    = lane & 3;

    for (int layer = 0; layer < 4; layer++) {
        const int nch = (layer == 0) ? 2 : 4;
        const int cb  = (layer == 0) ? 0 : (2 + (layer - 1) * 4);

        float C[2][8][4];
#pragma unroll
        for (int mi = 0; mi < 2; mi++)
#pragma unroll
            for (int ni = 0; ni < 8; ni++)
#pragma unroll
                for (int j = 0; j < 4; j++) C[mi][ni][j] = 0.f;

        for (int c = 0; c < nch; c++) {
            const int gc  = cb + c;
            const int buf = gc & 1;
            if (gc + 1 < NCHUNKS) { stage(gc + 1); cp_wait<1>(); }
            else                  { cp_wait<0>(); }
            __syncthreads();

            const uint32_t* B = Bs + buf * KPC * BSTRIDE2;
#pragma unroll
            for (int ks2 = 0; ks2 < KPC; ks2 += 8) {
                const int kpA = c * KPC + ks2;
                uint32_t a[2][4];
#pragma unroll
                for (int mi = 0; mi < 2; mi++) {
                    int r = wm + mi * 16 + g;
                    a[mi][0] = As[r * ASTRIDE2 + kpA + q];
                    a[mi][1] = As[(r + 8) * ASTRIDE2 + kpA + q];
                    a[mi][2] = As[r * ASTRIDE2 + kpA + q + 4];
                    a[mi][3] = As[(r + 8) * ASTRIDE2 + kpA + q + 4];
                }
                uint32_t b[8][2];
#pragma unroll
                for (int ni = 0; ni < 8; ni++) {
                    int cc = wn + ni * 8 + g;
                    b[ni][0] = B[(ks2 + q) * BSTRIDE2 + cc];
                    b[ni][1] = B[(ks2 + q + 4) * BSTRIDE2 + cc];
                }
#pragma unroll
                for (int mi = 0; mi < 2; mi++)
#pragma unroll
                    for (int ni = 0; ni < 8; ni++)
                        mma16(C[mi][ni], a[mi], b[ni]);
            }
            __syncthreads();
        }

        float bias[8][2];
        if (layer > 0) {
            const float* bp = bs + (size_t)(layer - 1) * OUT;
#pragma unroll
            for (int ni = 0; ni < 8; ni++) {
                int cc = wn + ni * 8 + (q << 1);
                bias[ni][0] = __ldg(bp + cc);
                bias[ni][1] = __ldg(bp + cc + 1);
            }
        }

#pragma unroll
        for (int mi = 0; mi < 2; mi++) {
#pragma unroll
            for (int ni = 0; ni < 8; ni++) {
                float v[4];
#pragma unroll
                for (int j = 0; j < 4; j++) {
                    float xv = C[mi][ni][j];
                    if (layer > 0) {
                        xv += bias[ni][j & 1];
                        xv = xv / (1.f + __expf(-xv));
                    }
                    v[j] = xv;
                }
                int r  = wm + mi * 16 + g;
                int cc = wn + ni * 8 + (q << 1);
                if (layer < 3) {
                    As[r * ASTRIDE2 + (cc >> 1)]       = pack_h2(v[0], v[1]);
                    As[(r + 8) * ASTRIDE2 + (cc >> 1)] = pack_h2(v[2], v[3]);
                } else {
                    if (row0 + r < n_nodes)
                        *(float2*)(out + (size_t)(row0 + r) * OUT + cc) = make_float2(v[0], v[1]);
                    if (row0 + r + 8 < n_nodes)
                        *(float2*)(out + (size_t)(row0 + r + 8) * OUT + cc) = make_float2(v[2], v[3]);
                }
            }
        }
        __syncthreads();
    }
}

// ---------------------------------------------------------------------------
extern "C" void kernel_launch(void* const* d_in, const int* in_sizes, int n_in,
                              void* d_out, int out_size) {
    const float* x      = (const float*)d_in[0];
    const float* rbf    = (const float*)d_in[1];
    const void*  idx    = d_in[2];
    const float* W_rbf  = (const float*)d_in[3];
    const float* W_down = (const float*)d_in[4];
    const float* Ws     = (const float*)d_in[5];
    const float* bs     = (const float*)d_in[6];
    float* out = (float*)d_out;

    const int E       = in_sizes[0] / HIDDEN;
    const int n_nodes = out_size / OUT;
    const int nb      = (n_nodes + 255) / 256;     // scan blocks (<=196, fits 256)

    void* cnt_ptr = nullptr;
    cudaGetSymbolAddress(&cnt_ptr, g_cnt);
    cudaMemsetAsync(cnt_ptr, 0, NODES_MAX * sizeof(int));

    prep_kernel<<<(NCHUNKS * CHUNK_U32 + 255) / 256, 256>>>(
        W_down, Ws, (const long long*)idx, n_nodes);
    count_kernel<<<(E + 255) / 256, 256>>>(idx, E);
    scanA_kernel<<<nb, 256>>>(nb);
    scanB_kernel<<<1, 256>>>(nb);
    scanC_kernel<<<nb, 256>>>(nb);
    permute_kernel<<<(E + 255) / 256, 256>>>(idx, E);
    gather_kernel<<<(n_nodes * 32 + 255) / 256, 256>>>(x, rbf, W_rbf, n_nodes);

    const int smem_bytes = (TM * ASTRIDE2 + 2 * KPC * BSTRIDE2) * (int)sizeof(uint32_t);
    cudaFuncSetAttribute(mlp_kernel, cudaFuncAttributeMaxDynamicSharedMemorySize, smem_bytes);
    const int grid = (n_nodes + TM - 1) / TM;
    mlp_kernel<<<grid, 256, smem_bytes>>>(bs, out, n_nodes);
}